// round 14
// baseline (speedup 1.0000x reference)
#include <cuda_runtime.h>
#include <cstdint>
#include <cstddef>

// Problem constants: B=4, C=128, N=64, HID=1536, PROJ=768
// featT: [128, 768] (k-major for GEMM1), hT: [1536, 768] (k-major for GEMM2)

__device__ float g_featT[128 * 768];
__device__ float g_hT[1536 * 768];
__device__ float g_part[6 * 768 * 768];

__device__ __forceinline__ void redadd(float* p, float v) {
    asm volatile("red.global.add.f32 [%0], %1;" :: "l"(p), "f"(v) : "memory");
}

// ---------------------------------------------------------------------------
__global__ void __launch_bounds__(256) init_feat() {
    const int i = blockIdx.x * 256 + threadIdx.x;   // 24576 float4
    reinterpret_cast<float4*>(g_featT)[i] = make_float4(0.f, 0.f, 0.f, 0.f);
}

// ---------------------------------------------------------------------------
// Kernel 1: streaming reduction, 4096 CTAs (1/8 slab = 8 d-planes, 128 KB).
// (unchanged from R12)
// ---------------------------------------------------------------------------
__global__ void __launch_bounds__(256, 4) reduce_kernel(const float* __restrict__ x) {
    __shared__ float dpart[8 * 64];
    __shared__ float ss_s[64];
    __shared__ float sa_s[64];
    const int tid = threadIdx.x;
    if (tid < 64) { ss_s[tid] = 0.f; sa_s[tid] = 0.f; }
    __syncthreads();

    const int slab = blockIdx.x >> 3;
    const int p    = blockIdx.x & 7;
    const int warp = tid >> 5;
    const int lane = tid & 31;
    const int q    = warp & 3;
    const int half = warp >> 2;
    const int j    = lane & 15;
    const int u    = lane >> 4;

    const float4* base = reinterpret_cast<const float4*>(x) + (size_t)slab * 65536
                         + (size_t)(8 * p) * 1024 + (16 * q + u) * 16 + j;

    float hreg[8];
#pragma unroll
    for (int i = 0; i < 8; ++i) hreg[i] = 0.f;
    float w0 = 0.f, w1 = 0.f, w2 = 0.f, w3 = 0.f;

#pragma unroll
    for (int dd = 0; dd < 4; ++dd) {
        const int dl = 2 * dd + half;
        const float4* pp = base + dl * 1024;
        float dacc = 0.f;
#pragma unroll
        for (int i = 0; i < 8; ++i) {
            float4 v = __ldcs(pp + i * 32);
            float s0 = v.x * v.x, s1 = v.y * v.y, s2 = v.z * v.z, s3 = v.w * v.w;
            w0 += s0; w1 += s1; w2 += s2; w3 += s3;
            float sm = (s0 + s1) + (s2 + s3);
            hreg[i] += sm;
            dacc    += sm;
        }
        dacc += __shfl_xor_sync(0xffffffffu, dacc, 16);
        if (lane < 16) dpart[dl * 64 + q * 16 + j] = dacc;
    }

#pragma unroll
    for (int i = 0; i < 8; ++i) {
        float v = hreg[i];
        v += __shfl_xor_sync(0xffffffffu, v, 1);
        v += __shfl_xor_sync(0xffffffffu, v, 2);
        v += __shfl_xor_sync(0xffffffffu, v, 4);
        v += __shfl_xor_sync(0xffffffffu, v, 8);
        if (j == 0) atomicAdd(&ss_s[16 * q + u + 2 * i], v);
    }

    atomicAdd(&sa_s[4 * j + 0], w0);
    atomicAdd(&sa_s[4 * j + 1], w1);
    atomicAdd(&sa_s[4 * j + 2], w2);
    atomicAdd(&sa_s[4 * j + 3], w3);

    __syncthreads();

    const int b = slab >> 7;
    const int c = slab & 127;
    float* frow = g_featT + (size_t)c * 768 + b * 192;
    if (tid < 32) {
        const int dl = tid >> 2;
        const int qq = tid & 3;
        const float4* dp = reinterpret_cast<const float4*>(&dpart[dl * 64 + qq * 16]);
        float s = 0.f;
#pragma unroll
        for (int k = 0; k < 4; ++k) {
            float4 v = dp[k];
            s += (v.x + v.y) + (v.z + v.w);
        }
        s += __shfl_xor_sync(0xffffffffu, s, 1);
        s += __shfl_xor_sync(0xffffffffu, s, 2);
        if (qq == 0) frow[8 * p + dl] = s * (1.0f / 4096.0f);
    }
    if (tid < 64) {
        redadd(&frow[64 + tid], ss_s[tid] * (1.0f / 4096.0f));
    } else if (tid < 128) {
        redadd(&frow[128 + (tid - 64)], sa_s[tid - 64] * (1.0f / 4096.0f));
    }
}

// ---------------------------------------------------------------------------
// FFMA2 SGEMM (R12 inner loop, template occupancy OCC):
// tile (64*GM)m x (64*GN)n, BK=16, 256 threads, k-major operands, 3-stage
// cp.async ring with wait_group 1.
// GEMM2 config: GM=2, GN=1, OCC=3 -> 24 warps/SM (6/SMSP) hide the k-step
// boundary scoreboard stalls that 4 warps/SMSP could not (R12 fma=64%).
// TOUT: transposed epilogue bias+relu -> C[n][m] (row stride Mtot).
// !TOUT: fp32 partials at C + z*768*768.
// ---------------------------------------------------------------------------
__device__ __forceinline__ void fma2(unsigned long long& d,
                                     unsigned long long a,
                                     unsigned long long b) {
    asm("fma.rn.f32x2 %0, %1, %2, %0;" : "+l"(d) : "l"(a), "l"(b));
}
__device__ __forceinline__ unsigned long long pack2(float v) {
    unsigned long long r;
    asm("mov.b64 %0, {%1, %1};" : "=l"(r) : "f"(v));
    return r;
}
__device__ __forceinline__ float2 u2f(unsigned long long v) {
    float2 f;
    asm("mov.b64 {%0,%1}, %2;" : "=f"(f.x), "=f"(f.y) : "l"(v));
    return f;
}
__device__ __forceinline__ void cp_async16(uint32_t dst, const void* src) {
    asm volatile("cp.async.ca.shared.global [%0], [%1], 16;"
                 :: "r"(dst), "l"(src) : "memory");
}

template <int GM, int GN, bool TOUT, int OCC>
__global__ void __launch_bounds__(256, OCC) gemm_kernel(const float* __restrict__ At,
                                                        const float* __restrict__ Bw,
                                                        const float* __restrict__ bias,
                                                        float* __restrict__ C,
                                                        int Mtot, int Nn, int Kc) {
    constexpr int AROW = 64 * GM;
    constexpr int BROW = 64 * GN;
    __shared__ float As[3][16][AROW];
    __shared__ float Bs[3][16][BROW];

    const int tid = threadIdx.x;
    const int tx = tid & 15;
    const int ty = tid >> 4;
    const int m0 = blockIdx.y * AROW;
    const int n0 = blockIdx.x * BROW;
    const int kstart = blockIdx.z * Kc;
    const int T = Kc >> 4;            // >= 2 for all calls

    unsigned long long acc[2 * GM][4 * GN];
#pragma unroll
    for (int i = 0; i < 2 * GM; ++i)
#pragma unroll
        for (int qn = 0; qn < 4 * GN; ++qn) acc[i][qn] = 0ull;

    const unsigned as_base = (unsigned)__cvta_generic_to_shared(&As[0][0][0]);
    const unsigned bs_base = (unsigned)__cvta_generic_to_shared(&Bs[0][0][0]);
    const unsigned a_rd = as_base + (unsigned)(ty * 16);
    const unsigned b_rd = bs_base + (unsigned)(tx * 16);
    constexpr unsigned ASTAGE_B = 16 * AROW * 4;
    constexpr unsigned BSTAGE_B = 16 * BROW * 4;

    const float* Abase = At + (size_t)kstart * Mtot + m0;
    const float* Bbase = Bw + (size_t)kstart * Nn + n0;

#define FILL_TILE(stage, trow)                                                 \
    do {                                                                       \
        _Pragma("unroll")                                                      \
        for (int i = 0; i < GM; ++i) {                                         \
            const int idx = tid + 256 * i;                                     \
            const int r = idx / (16 * GM);                                     \
            const int f4 = idx % (16 * GM);                                    \
            cp_async16(as_base + (unsigned)((stage) * ASTAGE_B +               \
                                            (r * AROW + 4 * f4) * 4),          \
                       Abase + (size_t)((trow) + r) * Mtot + 4 * f4);          \
        }                                                                      \
        _Pragma("unroll")                                                      \
        for (int i = 0; i < GN; ++i) {                                         \
            const int idx = tid + 256 * i;                                     \
            const int r = idx / (16 * GN);                                     \
            const int f4 = idx % (16 * GN);                                    \
            cp_async16(bs_base + (unsigned)((stage) * BSTAGE_B +               \
                                            (r * BROW + 4 * f4) * 4),          \
                       Bbase + (size_t)((trow) + r) * Nn + 4 * f4);            \
        }                                                                      \
        asm volatile("cp.async.commit_group;" ::: "memory");                   \
    } while (0)

    // prologue: stages 0,1 filled; stage 0 guaranteed complete
    FILL_TILE(0, 0);
    FILL_TILE(1, 16);
    asm volatile("cp.async.wait_group 1;" ::: "memory");
    __syncthreads();

    int st = 0, st2 = 2;     // st = t%3, st2 = (t+2)%3
    for (int t = 0; ; ) {
        const bool have2 = (t + 2 < T);
        if (have2) FILL_TILE(st2, 16 * (t + 2));

        const unsigned ao = a_rd + (unsigned)(st * ASTAGE_B);
        const unsigned bo = b_rd + (unsigned)(st * BSTAGE_B);
#pragma unroll
        for (int k = 0; k < 16; ++k) {
            unsigned long long am[2 * GM];
            float bf[4 * GN];
#pragma unroll
            for (int g = 0; g < GM; ++g)
                asm volatile("ld.shared.v2.b64 {%0,%1},[%2];"
                             : "=l"(am[2 * g]), "=l"(am[2 * g + 1])
                             : "r"(ao + (unsigned)(k * AROW * 4 + g * 256)));
#pragma unroll
            for (int g = 0; g < GN; ++g)
                asm volatile("ld.shared.v4.f32 {%0,%1,%2,%3},[%4];"
                             : "=f"(bf[4 * g]), "=f"(bf[4 * g + 1]),
                               "=f"(bf[4 * g + 2]), "=f"(bf[4 * g + 3])
                             : "r"(bo + (unsigned)(k * BROW * 4 + g * 256)));
            unsigned long long bb[4 * GN];
#pragma unroll
            for (int qn = 0; qn < 4 * GN; ++qn) bb[qn] = pack2(bf[qn]);
#pragma unroll
            for (int i = 0; i < 2 * GM; ++i) {
#pragma unroll
                for (int qn = 0; qn < 4 * GN; ++qn) fma2(acc[i][qn], am[i], bb[qn]);
            }
        }

        if (t + 1 >= T) break;
        if (have2) asm volatile("cp.async.wait_group 1;" ::: "memory");
        else       asm volatile("cp.async.wait_group 0;" ::: "memory");
        __syncthreads();
        ++t;
        st = (st == 2) ? 0 : st + 1;
        st2 = (st2 == 2) ? 0 : st2 + 1;
    }
#undef FILL_TILE

    if (TOUT) {
        // transposed epilogue: C[n][m], row stride Mtot, bias+relu.
#pragma unroll
        for (int gn = 0; gn < GN; ++gn) {
#pragma unroll
            for (int q = 0; q < 4; ++q) {
                const int n = n0 + 64 * gn + 4 * tx + q;
                const float bq = bias[n];
#pragma unroll
                for (int g = 0; g < GM; ++g) {
                    float2 e0 = u2f(acc[2 * g][4 * gn + q]);
                    float2 e1 = u2f(acc[2 * g + 1][4 * gn + q]);
                    float4 v = make_float4(fmaxf(e0.x + bq, 0.f), fmaxf(e0.y + bq, 0.f),
                                           fmaxf(e1.x + bq, 0.f), fmaxf(e1.y + bq, 0.f));
                    *reinterpret_cast<float4*>(
                        &C[(size_t)n * Mtot + m0 + 64 * g + 4 * ty]) = v;
                }
            }
        }
    } else {
        float* Cout = C + (size_t)blockIdx.z * 768 * 768;
#pragma unroll
        for (int i = 0; i < 2 * GM; ++i) {
            const int mrow = m0 + 64 * (i >> 1) + 4 * ty + 2 * (i & 1);
#pragma unroll
            for (int gn = 0; gn < GN; ++gn) {
                float2 f0 = u2f(acc[i][4 * gn + 0]);
                float2 f1 = u2f(acc[i][4 * gn + 1]);
                float2 f2 = u2f(acc[i][4 * gn + 2]);
                float2 f3 = u2f(acc[i][4 * gn + 3]);
                float4 lo0 = make_float4(f0.x, f1.x, f2.x, f3.x);
                float4 lo1 = make_float4(f0.y, f1.y, f2.y, f3.y);
                *reinterpret_cast<float4*>(&Cout[(size_t)mrow * Nn + n0 + 64 * gn + 4 * tx]) = lo0;
                *reinterpret_cast<float4*>(&Cout[(size_t)(mrow + 1) * Nn + n0 + 64 * gn + 4 * tx]) = lo1;
            }
        }
    }
}

// ---------------------------------------------------------------------------
// Combine split-K=6 partials + bias; 2 float4/thread, 6-deep MLP per f4.
// ---------------------------------------------------------------------------
__global__ void __launch_bounds__(256) combine_kernel(const float* __restrict__ part,
                                                      const float* __restrict__ bias,
                                                      float* __restrict__ out) {
    const float4* p = reinterpret_cast<const float4*>(part);
#pragma unroll
    for (int rep = 0; rep < 2; ++rep) {
        const int i = blockIdx.x * 512 + rep * 256 + threadIdx.x;
        float4 v[6];
#pragma unroll
        for (int z = 0; z < 6; ++z) v[z] = p[i + z * 147456];
        float4 bb = reinterpret_cast<const float4*>(bias)[i % 192];
        float4 r;
        r.x = (((v[0].x + v[1].x) + (v[2].x + v[3].x)) + (v[4].x + v[5].x)) + bb.x;
        r.y = (((v[0].y + v[1].y) + (v[2].y + v[3].y)) + (v[4].y + v[5].y)) + bb.y;
        r.z = (((v[0].z + v[1].z) + (v[2].z + v[3].z)) + (v[4].z + v[5].z)) + bb.z;
        r.w = (((v[0].w + v[1].w) + (v[2].w + v[3].w)) + (v[4].w + v[5].w)) + bb.w;
        reinterpret_cast<float4*>(out)[i] = r;
    }
}

// ---------------------------------------------------------------------------
extern "C" void kernel_launch(void* const* d_in, const int* in_sizes, int n_in,
                              void* d_out, int out_size) {
    const float* x  = (const float*)d_in[0];
    const float* W1 = (const float*)d_in[1];
    const float* b1 = (const float*)d_in[2];
    const float* W2 = (const float*)d_in[3];
    const float* b2 = (const float*)d_in[4];
    float* out = (float*)d_out;

    float* featT = nullptr;
    float* hT = nullptr;
    float* part = nullptr;
    cudaGetSymbolAddress((void**)&featT, g_featT);
    cudaGetSymbolAddress((void**)&hT, g_hT);
    cudaGetSymbolAddress((void**)&part, g_part);

    // 0) zero featT (h/w planes are RED targets)
    init_feat<<<96, 256>>>();

    // 1) reduction: 4096 CTAs (1/8 slab each) -> featT [128][768]
    reduce_kernel<<<4096, 256>>>(x);

    // 2) hT = relu(feat @ W1 + b1)^T: tile 64x64, grid 24x12 = 288 CTAs
    gemm_kernel<1, 1, true, 2><<<dim3(24, 12, 1), 256>>>(featT, W1, b1, hT,
                                                         768, 1536, 128);

    // 3) partials = h @ W2 (split-K=6): tile 128x64 -> 12x6x6 = 432 CTAs,
    //    3 CTAs/SM (6 warps/SMSP)
    gemm_kernel<2, 1, false, 3><<<dim3(12, 6, 6), 256>>>(hT, W2, nullptr, part,
                                                         768, 768, 256);

    // 4) out = sum(6 partials) + b2
    combine_kernel<<<288, 256>>>(part, b2, out);
}

// round 15
// speedup vs baseline: 1.0347x; 1.0347x over previous
#include <cuda_runtime.h>
#include <cstdint>
#include <cstddef>

// Problem constants: B=4, C=128, N=64, HID=1536, PROJ=768
// featT: [128, 768] (k-major for GEMM1), hT: [1536, 768] (k-major for GEMM2)

__device__ float g_featT[128 * 768];
__device__ float g_hT[1536 * 768];
__device__ float g_part[8 * 768 * 768];

__device__ __forceinline__ void redadd(float* p, float v) {
    asm volatile("red.global.add.f32 [%0], %1;" :: "l"(p), "f"(v) : "memory");
}

// ---------------------------------------------------------------------------
__global__ void __launch_bounds__(256) init_feat() {
    const int i = blockIdx.x * 256 + threadIdx.x;   // 24576 float4
    reinterpret_cast<float4*>(g_featT)[i] = make_float4(0.f, 0.f, 0.f, 0.f);
}

// ---------------------------------------------------------------------------
// Kernel 1: streaming reduction, 4096 CTAs (1/8 slab = 8 d-planes, 128 KB).
// (unchanged from R12)
// ---------------------------------------------------------------------------
__global__ void __launch_bounds__(256, 4) reduce_kernel(const float* __restrict__ x) {
    __shared__ float dpart[8 * 64];
    __shared__ float ss_s[64];
    __shared__ float sa_s[64];
    const int tid = threadIdx.x;
    if (tid < 64) { ss_s[tid] = 0.f; sa_s[tid] = 0.f; }
    __syncthreads();

    const int slab = blockIdx.x >> 3;
    const int p    = blockIdx.x & 7;
    const int warp = tid >> 5;
    const int lane = tid & 31;
    const int q    = warp & 3;
    const int half = warp >> 2;
    const int j    = lane & 15;
    const int u    = lane >> 4;

    const float4* base = reinterpret_cast<const float4*>(x) + (size_t)slab * 65536
                         + (size_t)(8 * p) * 1024 + (16 * q + u) * 16 + j;

    float hreg[8];
#pragma unroll
    for (int i = 0; i < 8; ++i) hreg[i] = 0.f;
    float w0 = 0.f, w1 = 0.f, w2 = 0.f, w3 = 0.f;

#pragma unroll
    for (int dd = 0; dd < 4; ++dd) {
        const int dl = 2 * dd + half;
        const float4* pp = base + dl * 1024;
        float dacc = 0.f;
#pragma unroll
        for (int i = 0; i < 8; ++i) {
            float4 v = __ldcs(pp + i * 32);
            float s0 = v.x * v.x, s1 = v.y * v.y, s2 = v.z * v.z, s3 = v.w * v.w;
            w0 += s0; w1 += s1; w2 += s2; w3 += s3;
            float sm = (s0 + s1) + (s2 + s3);
            hreg[i] += sm;
            dacc    += sm;
        }
        dacc += __shfl_xor_sync(0xffffffffu, dacc, 16);
        if (lane < 16) dpart[dl * 64 + q * 16 + j] = dacc;
    }

#pragma unroll
    for (int i = 0; i < 8; ++i) {
        float v = hreg[i];
        v += __shfl_xor_sync(0xffffffffu, v, 1);
        v += __shfl_xor_sync(0xffffffffu, v, 2);
        v += __shfl_xor_sync(0xffffffffu, v, 4);
        v += __shfl_xor_sync(0xffffffffu, v, 8);
        if (j == 0) atomicAdd(&ss_s[16 * q + u + 2 * i], v);
    }

    atomicAdd(&sa_s[4 * j + 0], w0);
    atomicAdd(&sa_s[4 * j + 1], w1);
    atomicAdd(&sa_s[4 * j + 2], w2);
    atomicAdd(&sa_s[4 * j + 3], w3);

    __syncthreads();

    const int b = slab >> 7;
    const int c = slab & 127;
    float* frow = g_featT + (size_t)c * 768 + b * 192;
    if (tid < 32) {
        const int dl = tid >> 2;
        const int qq = tid & 3;
        const float4* dp = reinterpret_cast<const float4*>(&dpart[dl * 64 + qq * 16]);
        float s = 0.f;
#pragma unroll
        for (int k = 0; k < 4; ++k) {
            float4 v = dp[k];
            s += (v.x + v.y) + (v.z + v.w);
        }
        s += __shfl_xor_sync(0xffffffffu, s, 1);
        s += __shfl_xor_sync(0xffffffffu, s, 2);
        if (qq == 0) frow[8 * p + dl] = s * (1.0f / 4096.0f);
    }
    if (tid < 64) {
        redadd(&frow[64 + tid], ss_s[tid] * (1.0f / 4096.0f));
    } else if (tid < 128) {
        redadd(&frow[128 + (tid - 64)], sa_s[tid - 64] * (1.0f / 4096.0f));
    }
}

// ---------------------------------------------------------------------------
// FFMA2 SGEMM: R12 inner-loop shape (128x128, GM=GN=2, 4 LDS / 32 FFMA2 per
// k-step) with BK=32 and a 2-stage cp.async ring:
//  - 6 barriers/CTA instead of 12 (GEMM2)
//  - the end-of-tile wait_group 0 sits a full 32-k compute after its fill
//  - B LDS issued before A LDS (B has the longer LDS->pack->FMA chain)
// TOUT: transposed epilogue bias+relu -> C[n][m] (row stride Mtot).
// !TOUT: fp32 partials at C + z*768*768.
// ---------------------------------------------------------------------------
__device__ __forceinline__ void fma2(unsigned long long& d,
                                     unsigned long long a,
                                     unsigned long long b) {
    asm("fma.rn.f32x2 %0, %1, %2, %0;" : "+l"(d) : "l"(a), "l"(b));
}
__device__ __forceinline__ unsigned long long pack2(float v) {
    unsigned long long r;
    asm("mov.b64 %0, {%1, %1};" : "=l"(r) : "f"(v));
    return r;
}
__device__ __forceinline__ float2 u2f(unsigned long long v) {
    float2 f;
    asm("mov.b64 {%0,%1}, %2;" : "=f"(f.x), "=f"(f.y) : "l"(v));
    return f;
}
__device__ __forceinline__ void cp_async16(uint32_t dst, const void* src) {
    asm volatile("cp.async.ca.shared.global [%0], [%1], 16;"
                 :: "r"(dst), "l"(src) : "memory");
}

template <int GM, int GN, bool TOUT>
__global__ void __launch_bounds__(256, 2) gemm_kernel(const float* __restrict__ At,
                                                      const float* __restrict__ Bw,
                                                      const float* __restrict__ bias,
                                                      float* __restrict__ C,
                                                      int Mtot, int Nn, int Kc) {
    constexpr int KB = 32;                       // k per tile
    constexpr int AROW = 64 * GM;
    constexpr int BROW = 64 * GN;
    __shared__ float As[2][KB][AROW];
    __shared__ float Bs[2][KB][BROW];

    const int tid = threadIdx.x;
    const int tx = tid & 15;
    const int ty = tid >> 4;
    const int m0 = blockIdx.y * AROW;
    const int n0 = blockIdx.x * BROW;
    const int kstart = blockIdx.z * Kc;
    const int T = Kc / KB;            // >= 2 for all calls

    unsigned long long acc[2 * GM][4 * GN];
#pragma unroll
    for (int i = 0; i < 2 * GM; ++i)
#pragma unroll
        for (int qn = 0; qn < 4 * GN; ++qn) acc[i][qn] = 0ull;

    const unsigned as_base = (unsigned)__cvta_generic_to_shared(&As[0][0][0]);
    const unsigned bs_base = (unsigned)__cvta_generic_to_shared(&Bs[0][0][0]);
    const unsigned a_rd = as_base + (unsigned)(ty * 16);
    const unsigned b_rd = bs_base + (unsigned)(tx * 16);
    constexpr unsigned ASTAGE_B = KB * AROW * 4;
    constexpr unsigned BSTAGE_B = KB * BROW * 4;

    const float* Abase = At + (size_t)kstart * Mtot + m0;
    const float* Bbase = Bw + (size_t)kstart * Nn + n0;

#define FILL_TILE(stage, trow)                                                 \
    do {                                                                       \
        _Pragma("unroll")                                                      \
        for (int i = 0; i < (KB / 16) * GM; ++i) {                             \
            const int idx = tid + 256 * i;                                     \
            const int r = idx / (16 * GM);                                     \
            const int f4 = idx % (16 * GM);                                    \
            cp_async16(as_base + (unsigned)((stage) * ASTAGE_B +               \
                                            (r * AROW + 4 * f4) * 4),          \
                       Abase + (size_t)((trow) + r) * Mtot + 4 * f4);          \
        }                                                                      \
        _Pragma("unroll")                                                      \
        for (int i = 0; i < (KB / 16) * GN; ++i) {                             \
            const int idx = tid + 256 * i;                                     \
            const int r = idx / (16 * GN);                                     \
            const int f4 = idx % (16 * GN);                                    \
            cp_async16(bs_base + (unsigned)((stage) * BSTAGE_B +               \
                                            (r * BROW + 4 * f4) * 4),          \
                       Bbase + (size_t)((trow) + r) * Nn + 4 * f4);            \
        }                                                                      \
        asm volatile("cp.async.commit_group;" ::: "memory");                   \
    } while (0)

    // prologue: tile 0
    FILL_TILE(0, 0);
    asm volatile("cp.async.wait_group 0;" ::: "memory");
    __syncthreads();

    for (int t = 0; ; ) {
        const int st = t & 1;
        const bool more = (t + 1 < T);
        if (more) FILL_TILE(st ^ 1, KB * (t + 1));

        const unsigned ao = a_rd + (unsigned)(st * ASTAGE_B);
        const unsigned bo = b_rd + (unsigned)(st * BSTAGE_B);
#pragma unroll
        for (int k = 0; k < KB; ++k) {
            unsigned long long am[2 * GM];
            float bf[4 * GN];
            // B first: longer dependency chain (LDS -> pack -> FMA)
#pragma unroll
            for (int g = 0; g < GN; ++g)
                asm volatile("ld.shared.v4.f32 {%0,%1,%2,%3},[%4];"
                             : "=f"(bf[4 * g]), "=f"(bf[4 * g + 1]),
                               "=f"(bf[4 * g + 2]), "=f"(bf[4 * g + 3])
                             : "r"(bo + (unsigned)(k * BROW * 4 + g * 256)));
#pragma unroll
            for (int g = 0; g < GM; ++g)
                asm volatile("ld.shared.v2.b64 {%0,%1},[%2];"
                             : "=l"(am[2 * g]), "=l"(am[2 * g + 1])
                             : "r"(ao + (unsigned)(k * AROW * 4 + g * 256)));
            unsigned long long bb[4 * GN];
#pragma unroll
            for (int qn = 0; qn < 4 * GN; ++qn) bb[qn] = pack2(bf[qn]);
#pragma unroll
            for (int i = 0; i < 2 * GM; ++i) {
#pragma unroll
                for (int qn = 0; qn < 4 * GN; ++qn) fma2(acc[i][qn], am[i], bb[qn]);
            }
        }

        if (!more) break;
        asm volatile("cp.async.wait_group 0;" ::: "memory");
        __syncthreads();
        ++t;
    }
#undef FILL_TILE

    if (TOUT) {
        // transposed epilogue: C[n][m], row stride Mtot, bias+relu.
#pragma unroll
        for (int gn = 0; gn < GN; ++gn) {
#pragma unroll
            for (int q = 0; q < 4; ++q) {
                const int n = n0 + 64 * gn + 4 * tx + q;
                const float bq = bias[n];
#pragma unroll
                for (int g = 0; g < GM; ++g) {
                    float2 e0 = u2f(acc[2 * g][4 * gn + q]);
                    float2 e1 = u2f(acc[2 * g + 1][4 * gn + q]);
                    float4 v = make_float4(fmaxf(e0.x + bq, 0.f), fmaxf(e0.y + bq, 0.f),
                                           fmaxf(e1.x + bq, 0.f), fmaxf(e1.y + bq, 0.f));
                    *reinterpret_cast<float4*>(
                        &C[(size_t)n * Mtot + m0 + 64 * g + 4 * ty]) = v;
                }
            }
        }
    } else {
        float* Cout = C + (size_t)blockIdx.z * 768 * 768;
#pragma unroll
        for (int i = 0; i < 2 * GM; ++i) {
            const int mrow = m0 + 64 * (i >> 1) + 4 * ty + 2 * (i & 1);
#pragma unroll
            for (int gn = 0; gn < GN; ++gn) {
                float2 f0 = u2f(acc[i][4 * gn + 0]);
                float2 f1 = u2f(acc[i][4 * gn + 1]);
                float2 f2 = u2f(acc[i][4 * gn + 2]);
                float2 f3 = u2f(acc[i][4 * gn + 3]);
                float4 lo0 = make_float4(f0.x, f1.x, f2.x, f3.x);
                float4 lo1 = make_float4(f0.y, f1.y, f2.y, f3.y);
                *reinterpret_cast<float4*>(&Cout[(size_t)mrow * Nn + n0 + 64 * gn + 4 * tx]) = lo0;
                *reinterpret_cast<float4*>(&Cout[(size_t)(mrow + 1) * Nn + n0 + 64 * gn + 4 * tx]) = lo1;
            }
        }
    }
}

// ---------------------------------------------------------------------------
// Combine split-K=8 partials + bias; 2 float4/thread, 8-deep MLP per f4.
// ---------------------------------------------------------------------------
__global__ void __launch_bounds__(256) combine_kernel(const float* __restrict__ part,
                                                      const float* __restrict__ bias,
                                                      float* __restrict__ out) {
    const float4* p = reinterpret_cast<const float4*>(part);
#pragma unroll
    for (int rep = 0; rep < 2; ++rep) {
        const int i = blockIdx.x * 512 + rep * 256 + threadIdx.x;
        float4 v[8];
#pragma unroll
        for (int z = 0; z < 8; ++z) v[z] = p[i + z * 147456];
        float4 bb = reinterpret_cast<const float4*>(bias)[i % 192];
        float4 r;
        r.x = (((v[0].x + v[1].x) + (v[2].x + v[3].x)) +
               ((v[4].x + v[5].x) + (v[6].x + v[7].x))) + bb.x;
        r.y = (((v[0].y + v[1].y) + (v[2].y + v[3].y)) +
               ((v[4].y + v[5].y) + (v[6].y + v[7].y))) + bb.y;
        r.z = (((v[0].z + v[1].z) + (v[2].z + v[3].z)) +
               ((v[4].z + v[5].z) + (v[6].z + v[7].z))) + bb.z;
        r.w = (((v[0].w + v[1].w) + (v[2].w + v[3].w)) +
               ((v[4].w + v[5].w) + (v[6].w + v[7].w))) + bb.w;
        reinterpret_cast<float4*>(out)[i] = r;
    }
}

// ---------------------------------------------------------------------------
extern "C" void kernel_launch(void* const* d_in, const int* in_sizes, int n_in,
                              void* d_out, int out_size) {
    const float* x  = (const float*)d_in[0];
    const float* W1 = (const float*)d_in[1];
    const float* b1 = (const float*)d_in[2];
    const float* W2 = (const float*)d_in[3];
    const float* b2 = (const float*)d_in[4];
    float* out = (float*)d_out;

    float* featT = nullptr;
    float* hT = nullptr;
    float* part = nullptr;
    cudaGetSymbolAddress((void**)&featT, g_featT);
    cudaGetSymbolAddress((void**)&hT, g_hT);
    cudaGetSymbolAddress((void**)&part, g_part);

    // 0) zero featT (h/w planes are RED targets)
    init_feat<<<96, 256>>>();

    // 1) reduction: 4096 CTAs (1/8 slab each) -> featT [128][768]
    reduce_kernel<<<4096, 256>>>(x);

    // 2) hT = relu(feat @ W1 + b1)^T: tile 64x64, grid 24x12 = 288 CTAs
    gemm_kernel<1, 1, true><<<dim3(24, 12, 1), 256>>>(featT, W1, b1, hT,
                                                      768, 1536, 128);

    // 3) partials = h @ W2 (split-K=8): tile 128x128, 6x6x8 = 288 CTAs
    gemm_kernel<2, 2, false><<<dim3(6, 6, 8), 256>>>(hT, W2, nullptr, part,
                                                     768, 768, 192);

    // 4) out = sum(8 partials) + b2
    combine_kernel<<<288, 256>>>(part, b2, out);
}

// round 16
// speedup vs baseline: 1.1377x; 1.0996x over previous
#include <cuda_runtime.h>
#include <cuda_bf16.h>
#include <cstdint>
#include <cstddef>

// B=4, C=128, N=64, HID=1536, PROJ=768
// feat fp32 [768][128]; hi/lo bf16 planes: f[768][128], w1t[1536][128],
// w2t[768][1536], h[768][1536]; partials fp32 [8][768][768].

__device__ float g_featf[768 * 128];
__device__ __align__(16) __nv_bfloat16 g_fh[768 * 128];
__device__ __align__(16) __nv_bfloat16 g_fl[768 * 128];
__device__ __align__(16) __nv_bfloat16 g_w1h[1536 * 128];
__device__ __align__(16) __nv_bfloat16 g_w1l[1536 * 128];
__device__ __align__(16) __nv_bfloat16 g_w2h[768 * 1536];
__device__ __align__(16) __nv_bfloat16 g_w2l[768 * 1536];
__device__ __align__(16) __nv_bfloat16 g_hh[768 * 1536];
__device__ __align__(16) __nv_bfloat16 g_hl[768 * 1536];
__device__ float g_part[8 * 768 * 768];

__device__ __forceinline__ void redadd(float* p, float v) {
    asm volatile("red.global.add.f32 [%0], %1;" :: "l"(p), "f"(v) : "memory");
}
__device__ __forceinline__ void cp_async16(uint32_t dst, const void* src) {
    asm volatile("cp.async.ca.shared.global [%0], [%1], 16;"
                 :: "r"(dst), "l"(src) : "memory");
}
__device__ __forceinline__ uint32_t bfpair(float x, float y) {
    __nv_bfloat162 p = __floats2bfloat162_rn(x, y);   // .x = low half = x
    return *reinterpret_cast<uint32_t*>(&p);
}
__device__ __forceinline__ float bflo(float v) {
    return v - __bfloat162float(__float2bfloat16(v));
}

// ---------------------------------------------------------------------------
__global__ void __launch_bounds__(256) init_featf() {
    const int i = blockIdx.x * 256 + threadIdx.x;   // 24576 f4
    reinterpret_cast<float4*>(g_featf)[i] = make_float4(0.f, 0.f, 0.f, 0.f);
}

// ---------------------------------------------------------------------------
// Reduce (R6/R12 proven): 4096 CTAs, out g_featf[m][c] fp32 (h/w via RED).
// ---------------------------------------------------------------------------
__global__ void __launch_bounds__(256, 4) reduce_kernel(const float* __restrict__ x) {
    __shared__ float dpart[8 * 64];
    __shared__ float ss_s[64];
    __shared__ float sa_s[64];
    const int tid = threadIdx.x;
    if (tid < 64) { ss_s[tid] = 0.f; sa_s[tid] = 0.f; }
    __syncthreads();

    const int slab = blockIdx.x >> 3;
    const int p    = blockIdx.x & 7;
    const int warp = tid >> 5;
    const int lane = tid & 31;
    const int q    = warp & 3;
    const int half = warp >> 2;
    const int j    = lane & 15;
    const int u    = lane >> 4;

    const float4* base = reinterpret_cast<const float4*>(x) + (size_t)slab * 65536
                         + (size_t)(8 * p) * 1024 + (16 * q + u) * 16 + j;

    float hreg[8];
#pragma unroll
    for (int i = 0; i < 8; ++i) hreg[i] = 0.f;
    float w0 = 0.f, w1 = 0.f, w2 = 0.f, w3 = 0.f;

#pragma unroll
    for (int dd = 0; dd < 4; ++dd) {
        const int dl = 2 * dd + half;
        const float4* pp = base + dl * 1024;
        float dacc = 0.f;
#pragma unroll
        for (int i = 0; i < 8; ++i) {
            float4 v = __ldcs(pp + i * 32);
            float s0 = v.x * v.x, s1 = v.y * v.y, s2 = v.z * v.z, s3 = v.w * v.w;
            w0 += s0; w1 += s1; w2 += s2; w3 += s3;
            float sm = (s0 + s1) + (s2 + s3);
            hreg[i] += sm;
            dacc    += sm;
        }
        dacc += __shfl_xor_sync(0xffffffffu, dacc, 16);
        if (lane < 16) dpart[dl * 64 + q * 16 + j] = dacc;
    }

#pragma unroll
    for (int i = 0; i < 8; ++i) {
        float v = hreg[i];
        v += __shfl_xor_sync(0xffffffffu, v, 1);
        v += __shfl_xor_sync(0xffffffffu, v, 2);
        v += __shfl_xor_sync(0xffffffffu, v, 4);
        v += __shfl_xor_sync(0xffffffffu, v, 8);
        if (j == 0) atomicAdd(&ss_s[16 * q + u + 2 * i], v);
    }

    atomicAdd(&sa_s[4 * j + 0], w0);
    atomicAdd(&sa_s[4 * j + 1], w1);
    atomicAdd(&sa_s[4 * j + 2], w2);
    atomicAdd(&sa_s[4 * j + 3], w3);

    __syncthreads();

    const int b = slab >> 7;
    const int c = slab & 127;
    if (tid < 32) {
        const int dl = tid >> 2;
        const int qq = tid & 3;
        const float4* dp = reinterpret_cast<const float4*>(&dpart[dl * 64 + qq * 16]);
        float s = 0.f;
#pragma unroll
        for (int k = 0; k < 4; ++k) {
            float4 v = dp[k];
            s += (v.x + v.y) + (v.z + v.w);
        }
        s += __shfl_xor_sync(0xffffffffu, s, 1);
        s += __shfl_xor_sync(0xffffffffu, s, 2);
        if (qq == 0)
            g_featf[(size_t)(b * 192 + 8 * p + dl) * 128 + c] = s * (1.0f / 4096.0f);
    }
    if (tid < 64) {
        redadd(&g_featf[(size_t)(b * 192 + 64 + tid) * 128 + c],
               ss_s[tid] * (1.0f / 4096.0f));
    } else if (tid < 128) {
        redadd(&g_featf[(size_t)(b * 192 + 128 + (tid - 64)) * 128 + c],
               sa_s[tid - 64] * (1.0f / 4096.0f));
    }
}

// ---------------------------------------------------------------------------
// feat fp32 -> bf16 hi/lo planes (same [m][c] layout). 24576 f4 elements.
// ---------------------------------------------------------------------------
__global__ void __launch_bounds__(256) split_feat_kernel() {
    const int i = blockIdx.x * 256 + threadIdx.x;
    float4 v = reinterpret_cast<const float4*>(g_featf)[i];
    uint2 hw, lw;
    hw.x = bfpair(v.x, v.y);
    hw.y = bfpair(v.z, v.w);
    lw.x = bfpair(bflo(v.x), bflo(v.y));
    lw.y = bfpair(bflo(v.z), bflo(v.w));
    reinterpret_cast<uint2*>(g_fh)[i] = hw;
    reinterpret_cast<uint2*>(g_fl)[i] = lw;
}

// ---------------------------------------------------------------------------
// Transpose + split: fp32 src [K][Nn] -> bf16 hi/lo [Nn][K].
// ---------------------------------------------------------------------------
__global__ void __launch_bounds__(256) transpose_split(const float* __restrict__ src,
                                                       int K, int Nn,
                                                       __nv_bfloat16* __restrict__ dhi,
                                                       __nv_bfloat16* __restrict__ dlo) {
    __shared__ float t[32][33];
    const int tx = threadIdx.x & 31;
    const int ty = threadIdx.x >> 5;   // 0..7
    const int n0 = blockIdx.x * 32;
    const int k0 = blockIdx.y * 32;
#pragma unroll
    for (int i = 0; i < 4; ++i)
        t[ty + 8 * i][tx] = src[(size_t)(k0 + ty + 8 * i) * Nn + n0 + tx];
    __syncthreads();
#pragma unroll
    for (int i = 0; i < 4; ++i) {
        float v = t[tx][ty + 8 * i];
        const size_t o = (size_t)(n0 + ty + 8 * i) * K + k0 + tx;
        __nv_bfloat16 h = __float2bfloat16(v);
        dhi[o] = h;
        dlo[o] = __float2bfloat16(v - __bfloat162float(h));
    }
}

// ---------------------------------------------------------------------------
// bf16-split GEMM via mma.sync.m16n8k16 (HMMA fallback path on sm_103).
// A hi/lo: [Mtot][K] bf16 k-contig. B hi/lo: [Nn][K] bf16 k-contig.
// D = Ah*Bh + Al*Bh + Ah*Bl (fp32 accum).
// CTA: (64*WM) m x 128 n, 8 warps (WM m-rows x 8/WM n-cols),
// warp tile 64m x (16*WM)n = 4 m16-tiles x (2*WM) n8-tiles.
// smem: k-chunks of 32 bf16/row, row stride 80B (16B pad -> ldmatrix
// conflict-free: banks (20*r)%32 distinct for r=0..7). 2-stage cp.async.
// Fragment maps (PTX ISA m16n8k16, g=lane>>2, t=lane&3):
//   A [m][k]: a0a1=(g,2t) a2a3=(g+8,2t) a4a5=(g,2t+8) a6a7=(g+8,2t+8)
//     -> ldmatrix.x4 rows: lanes0-7 m0-7@k0 | 8-15 m8-15@k0 | 16-23 m0-7@k8 | 24-31 m8-15@k8
//   B [n][k]: b0b1=(k=2t,n=g) b2b3=(k=2t+8,n=g)
//     -> ldmatrix.x4: lanes0-7 n0-7@k0 | 8-15 n0-7@k8 | 16-23 n8-15@k0 | 24-31 n8-15@k8
//        regs: r0,r1 = frag(n0-7); r2,r3 = frag(n8-15)
//   D: d0=(g,2t) d1=(g,2t+1) d2=(g+8,2t) d3=(g+8,2t+1)
// TOUT: bias+relu, split -> OutHi/OutLo bf16 [m][n] (stride Nn).
// !TOUT: fp32 partials at OutF + z*768*768.
// ---------------------------------------------------------------------------
#define LDMX4(r, addr) \
    asm volatile("ldmatrix.sync.aligned.m8n8.x4.shared.b16 {%0,%1,%2,%3}, [%4];" \
                 : "=r"((r)[0]), "=r"((r)[1]), "=r"((r)[2]), "=r"((r)[3]) \
                 : "r"(addr))

__device__ __forceinline__ void mma_bf16(float* d, const uint32_t* a, const uint32_t* b) {
    asm volatile(
        "mma.sync.aligned.m16n8k16.row.col.f32.bf16.bf16.f32 "
        "{%0,%1,%2,%3}, {%4,%5,%6,%7}, {%8,%9}, {%0,%1,%2,%3};"
        : "+f"(d[0]), "+f"(d[1]), "+f"(d[2]), "+f"(d[3])
        : "r"(a[0]), "r"(a[1]), "r"(a[2]), "r"(a[3]), "r"(b[0]), "r"(b[1]));
}

template <int WM, bool TOUT>
__global__ void __launch_bounds__(256) gemm_mma(
    const __nv_bfloat16* __restrict__ Ah, const __nv_bfloat16* __restrict__ Al,
    const __nv_bfloat16* __restrict__ Bh, const __nv_bfloat16* __restrict__ Bl,
    const float* __restrict__ bias,
    __nv_bfloat16* __restrict__ OutHi, __nv_bfloat16* __restrict__ OutLo,
    float* __restrict__ OutF,
    int K, int Nn, int Kc) {
    constexpr int MT = 4;
    constexpr int NT = 2 * WM;
    constexpr int NWARPN = 8 / WM;
    constexpr int AROWS = 64 * WM;
    constexpr unsigned ROWB = 80;               // 64B data + 16B pad
    constexpr unsigned APLANE = AROWS * ROWB;
    constexpr unsigned BPLANE = 128 * ROWB;
    constexpr unsigned STG = 2 * APLANE + 2 * BPLANE;

    extern __shared__ char smem[];
    const unsigned sb = (unsigned)__cvta_generic_to_shared(smem);

    const int tid = threadIdx.x;
    const int lane = tid & 31;
    const int w = tid >> 5;
    const int wm = w / NWARPN;
    const int wn = w % NWARPN;
    const int m0 = blockIdx.y * AROWS;
    const int n0 = blockIdx.x * 128;
    const int kstart = blockIdx.z * Kc;
    const int T = Kc >> 5;

    float d[MT][NT][4];
#pragma unroll
    for (int mt = 0; mt < MT; ++mt)
#pragma unroll
        for (int nt = 0; nt < NT; ++nt)
#pragma unroll
            for (int e = 0; e < 4; ++e) d[mt][nt][e] = 0.f;

    // ldmatrix per-lane offsets (within a stage)
    const unsigned a_off = (unsigned)((wm * 64 + (lane & 15)) * ROWB
                                      + ((lane >> 4) & 1) * 16);
    const unsigned b_off = (unsigned)(2 * APLANE
                                      + (wn * 16 * WM + ((lane >> 4) & 1) * 8 + (lane & 7)) * ROWB
                                      + ((lane >> 3) & 1) * 16);

#define FILL(stg_, kc_)                                                        \
    do {                                                                       \
        _Pragma("unroll")                                                      \
        for (int i = 0; i < WM; ++i) {                                         \
            const int idx = tid + 256 * i;                                     \
            const int r = idx >> 2, cc = idx & 3;                              \
            const unsigned doff = (unsigned)((stg_) * STG + r * ROWB + cc * 16);\
            const size_t soff = (size_t)(m0 + r) * K + (kc_) + cc * 8;         \
            cp_async16(sb + doff, Ah + soff);                                  \
            cp_async16(sb + doff + APLANE, Al + soff);                         \
        }                                                                      \
        _Pragma("unroll")                                                      \
        for (int i = 0; i < 2; ++i) {                                          \
            const int idx = tid + 256 * i;                                     \
            const int r = idx >> 2, cc = idx & 3;                              \
            const unsigned doff = (unsigned)((stg_) * STG + 2 * APLANE         \
                                             + r * ROWB + cc * 16);            \
            const size_t soff = (size_t)(n0 + r) * K + (kc_) + cc * 8;         \
            cp_async16(sb + doff, Bh + soff);                                  \
            cp_async16(sb + doff + BPLANE, Bl + soff);                         \
        }                                                                      \
        asm volatile("cp.async.commit_group;" ::: "memory");                   \
    } while (0)

    FILL(0, kstart);
    asm volatile("cp.async.wait_group 0;" ::: "memory");
    __syncthreads();

    for (int t = 0; ; ) {
        const int st = t & 1;
        const bool more = (t + 1 < T);
        if (more) FILL(st ^ 1, kstart + 32 * (t + 1));

        const unsigned abase = sb + (unsigned)st * STG + a_off;
        const unsigned bbase = sb + (unsigned)st * STG + b_off;
#pragma unroll
        for (int ks = 0; ks < 2; ++ks) {
            uint32_t ah[MT][4], al[MT][4], bh[NT][2], bl[NT][2];
#pragma unroll
            for (int mt = 0; mt < MT; ++mt) {
                LDMX4(ah[mt], abase + (unsigned)(mt * 16 * ROWB + ks * 32));
                LDMX4(al[mt], abase + (unsigned)(APLANE + mt * 16 * ROWB + ks * 32));
            }
#pragma unroll
            for (int gi = 0; gi < NT / 2; ++gi) {
                uint32_t r[4];
                LDMX4(r, bbase + (unsigned)(gi * 16 * ROWB + ks * 32));
                bh[2 * gi][0] = r[0]; bh[2 * gi][1] = r[1];
                bh[2 * gi + 1][0] = r[2]; bh[2 * gi + 1][1] = r[3];
                LDMX4(r, bbase + (unsigned)(BPLANE + gi * 16 * ROWB + ks * 32));
                bl[2 * gi][0] = r[0]; bl[2 * gi][1] = r[1];
                bl[2 * gi + 1][0] = r[2]; bl[2 * gi + 1][1] = r[3];
            }
#pragma unroll
            for (int mt = 0; mt < MT; ++mt) {
#pragma unroll
                for (int nt = 0; nt < NT; ++nt) {
                    mma_bf16(d[mt][nt], ah[mt], bh[nt]);
                    mma_bf16(d[mt][nt], al[mt], bh[nt]);
                    mma_bf16(d[mt][nt], ah[mt], bl[nt]);
                }
            }
        }

        if (!more) break;
        asm volatile("cp.async.wait_group 0;" ::: "memory");
        __syncthreads();
        ++t;
    }
#undef FILL

    const int g = lane >> 2;
    const int tq = lane & 3;
    if (TOUT) {
#pragma unroll
        for (int nt = 0; nt < NT; ++nt) {
            const int nb = n0 + wn * 16 * WM + nt * 8 + 2 * tq;
            const float b0 = bias[nb];
            const float b1 = bias[nb + 1];
#pragma unroll
            for (int mt = 0; mt < MT; ++mt) {
                const int mr = m0 + wm * 64 + mt * 16 + g;
                float v0 = fmaxf(d[mt][nt][0] + b0, 0.f);
                float v1 = fmaxf(d[mt][nt][1] + b1, 0.f);
                float v2 = fmaxf(d[mt][nt][2] + b0, 0.f);
                float v3 = fmaxf(d[mt][nt][3] + b1, 0.f);
                *reinterpret_cast<uint32_t*>(&OutHi[(size_t)mr * Nn + nb]) = bfpair(v0, v1);
                *reinterpret_cast<uint32_t*>(&OutLo[(size_t)mr * Nn + nb]) =
                    bfpair(bflo(v0), bflo(v1));
                *reinterpret_cast<uint32_t*>(&OutHi[(size_t)(mr + 8) * Nn + nb]) = bfpair(v2, v3);
                *reinterpret_cast<uint32_t*>(&OutLo[(size_t)(mr + 8) * Nn + nb]) =
                    bfpair(bflo(v2), bflo(v3));
            }
        }
    } else {
        float* Co = OutF + (size_t)blockIdx.z * 768 * 768;
#pragma unroll
        for (int nt = 0; nt < NT; ++nt) {
            const int nb = n0 + wn * 16 * WM + nt * 8 + 2 * tq;
#pragma unroll
            for (int mt = 0; mt < MT; ++mt) {
                const int mr = m0 + wm * 64 + mt * 16 + g;
                *reinterpret_cast<float2*>(&Co[(size_t)mr * Nn + nb]) =
                    make_float2(d[mt][nt][0], d[mt][nt][1]);
                *reinterpret_cast<float2*>(&Co[(size_t)(mr + 8) * Nn + nb]) =
                    make_float2(d[mt][nt][2], d[mt][nt][3]);
            }
        }
    }
}

// ---------------------------------------------------------------------------
// Combine split-K=8 partials + bias.
// ---------------------------------------------------------------------------
__global__ void __launch_bounds__(256) combine_kernel(const float* __restrict__ part,
                                                      const float* __restrict__ bias,
                                                      float* __restrict__ out) {
    const float4* p = reinterpret_cast<const float4*>(part);
#pragma unroll
    for (int rep = 0; rep < 2; ++rep) {
        const int i = blockIdx.x * 512 + rep * 256 + threadIdx.x;
        float4 v[8];
#pragma unroll
        for (int z = 0; z < 8; ++z) v[z] = p[i + z * 147456];
        float4 bb = reinterpret_cast<const float4*>(bias)[i % 192];
        float4 r;
        r.x = (((v[0].x + v[1].x) + (v[2].x + v[3].x)) +
               ((v[4].x + v[5].x) + (v[6].x + v[7].x))) + bb.x;
        r.y = (((v[0].y + v[1].y) + (v[2].y + v[3].y)) +
               ((v[4].y + v[5].y) + (v[6].y + v[7].y))) + bb.y;
        r.z = (((v[0].z + v[1].z) + (v[2].z + v[3].z)) +
               ((v[4].z + v[5].z) + (v[6].z + v[7].z))) + bb.z;
        r.w = (((v[0].w + v[1].w) + (v[2].w + v[3].w)) +
               ((v[4].w + v[5].w) + (v[6].w + v[7].w))) + bb.w;
        reinterpret_cast<float4*>(out)[i] = r;
    }
}

// ---------------------------------------------------------------------------
extern "C" void kernel_launch(void* const* d_in, const int* in_sizes, int n_in,
                              void* d_out, int out_size) {
    const float* x  = (const float*)d_in[0];
    const float* W1 = (const float*)d_in[1];
    const float* b1 = (const float*)d_in[2];
    const float* W2 = (const float*)d_in[3];
    const float* b2 = (const float*)d_in[4];
    float* out = (float*)d_out;

    __nv_bfloat16 *fh, *fl, *w1h, *w1l, *w2h, *w2l, *hh, *hl;
    float* part;
    cudaGetSymbolAddress((void**)&fh,  g_fh);
    cudaGetSymbolAddress((void**)&fl,  g_fl);
    cudaGetSymbolAddress((void**)&w1h, g_w1h);
    cudaGetSymbolAddress((void**)&w1l, g_w1l);
    cudaGetSymbolAddress((void**)&w2h, g_w2h);
    cudaGetSymbolAddress((void**)&w2l, g_w2l);
    cudaGetSymbolAddress((void**)&hh,  g_hh);
    cudaGetSymbolAddress((void**)&hl,  g_hl);
    cudaGetSymbolAddress((void**)&part, g_part);

    // smem: WM=1 -> 61440 B, WM=2 -> 81920 B
    static bool attr_set = false;
    if (!attr_set) {
        cudaFuncSetAttribute(gemm_mma<1, true>,
                             cudaFuncAttributeMaxDynamicSharedMemorySize, 61440);
        cudaFuncSetAttribute(gemm_mma<2, false>,
                             cudaFuncAttributeMaxDynamicSharedMemorySize, 81920);
        attr_set = true;
    }

    // 0) zero fp32 feat (RED target)
    init_featf<<<96, 256>>>();

    // 1) weight prep (independent of reduce)
    transpose_split<<<dim3(48, 4), 256>>>(W1, 128, 1536, w1h, w1l);
    transpose_split<<<dim3(24, 48), 256>>>(W2, 1536, 768, w2h, w2l);

    // 2) streaming reduction -> g_featf [768][128]
    reduce_kernel<<<4096, 256>>>(x);

    // 3) feat -> bf16 hi/lo
    split_feat_kernel<<<96, 256>>>();

    // 4) h = relu(feat @ W1 + b1) -> hh/hl bf16 [768][1536]
    //    CTA 64m x 128n, grid (1536/128, 768/64) = (12, 12)
    gemm_mma<1, true><<<dim3(12, 12, 1), 256, 61440>>>(
        fh, fl, w1h, w1l, b1, hh, hl, nullptr, 128, 1536, 128);

    // 5) partials = h @ W2 (split-K=8): CTA 128x128, grid (6, 6, 8)
    gemm_mma<2, false><<<dim3(6, 6, 8), 256, 81920>>>(
        hh, hl, w2h, w2l, nullptr, nullptr, nullptr, part, 1536, 768, 192);

    // 6) out = sum(8 partials) + b2
    combine_kernel<<<288, 256>>>(part, b2, out);
}